// round 2
// baseline (speedup 1.0000x reference)
#include <cuda_runtime.h>
#include <cuda_bf16.h>

#define NBLOCKS 1184
#define NTHREADS 256
#define EPS 0.0001f

__device__ double       g_partials[NBLOCKS];
__device__ unsigned int g_counter = 0;

// Per-row loss. z = clamp((x-u)/s, -3, 3) is the exact simplification of
// sqrt2*erfinv(2*clip(ndtr(t),eps,1-eps)-1) clipped to [-3,3], since
// Phi^-1(eps) = -3.719 < -3 (the eps clip never binds inside [-3,3]).
// nll = 0.5*t^2 + log(s) = 0.5*t^2 + param  (s = exp(param)).
__device__ __forceinline__ float row_loss(
    float ra, float rb,                       // pred_r
    float pu1, float ps1, float pu2, float ps2, float pu3, float ps3, // pred_params
    float r12, float r13, float r23,          // pred_corr
    float revert, float Rtop, float Top, float Close) // y_true
{
    float u1 = __expf(pu1), s1 = __expf(ps1);
    float u2 = __expf(pu2), s2 = __expf(ps2);
    float u3 = __expf(pu3), s3 = __expf(ps3);

    float t1 = (Rtop  - u1) * __fdividef(1.0f, fmaxf(s1, EPS));
    float t2 = (Top   - u2) * __fdividef(1.0f, fmaxf(s2, EPS));
    float t3 = (Close - u3) * __fdividef(1.0f, fmaxf(s3, EPS));
    float z1 = fminf(fmaxf(t1, -3.0f), 3.0f);
    float z2 = fminf(fmaxf(t2, -3.0f), 3.0f);
    float z3 = fminf(fmaxf(t3, -3.0f), 3.0f);

    float nll_sum = 0.5f * (t1 * t1 + t2 * t2 + t3 * t3) + (ps1 + ps2 + ps3);

    float detR = 1.0f + 2.0f * r12 * r13 * r23
               - r12 * r12 - r13 * r13 - r23 * r23;
    float inv_det = 1.0f / detR;
    float i00 = (1.0f - r23 * r23) * inv_det;
    float i01 = (r13 * r23 - r12) * inv_det;
    float i02 = (r12 * r23 - r13) * inv_det;
    float i11 = (1.0f - r13 * r13) * inv_det;
    float i12 = (r12 * r13 - r23) * inv_det;
    float i22 = (1.0f - r12 * r12) * inv_det;

    float exp_term = 0.5f * ((i00 - 1.0f) * z1 * z1
                           + (i11 - 1.0f) * z2 * z2
                           + (i22 - 1.0f) * z3 * z3)
                   + (i01 * z1 * z2 + i02 * z1 * z3 + i12 * z2 * z3);

    float c_gauss = 0.5f * __logf(fmaxf(detR, EPS)) + exp_term;
    float copula  = revert * (c_gauss + nll_sum);

    // cross-entropy: lse(a,b) - selected
    float m   = fmaxf(ra, rb);
    float lse = m + __logf(1.0f + __expf(-fabsf(ra - rb)));
    float sel = (revert != 0.0f) ? rb : ra;
    return (lse - sel) + copula;
}

__global__ __launch_bounds__(NTHREADS)
void gausscop_fused(const float* __restrict__ pred_r,
                    const float* __restrict__ pred_params,
                    const float* __restrict__ pred_corr,
                    const float* __restrict__ y_true,
                    float* __restrict__ out,
                    int n)
{
    const int npairs = n >> 1;
    const int stride = gridDim.x * blockDim.x;
    float acc = 0.0f;

    for (int p = blockIdx.x * blockDim.x + threadIdx.x; p < npairs; p += stride) {
        long lp = p;
        // pred_r: 2 rows = 4 floats, 16B aligned
        float4 R  = *(const float4*)(pred_r + 4 * lp);
        // pred_params: 2 rows = 12 floats = 3 x float4, 48p bytes -> 16B aligned
        const float4* pp = (const float4*)(pred_params + 12 * lp);
        float4 P0 = pp[0], P1 = pp[1], P2 = pp[2];
        // pred_corr: 2 rows = 6 floats = 3 x float2 (only 8B aligned)
        const float2* pc = (const float2*)(pred_corr + 6 * lp);
        float2 C0 = pc[0], C1 = pc[1], C2 = pc[2];
        // y_true: 2 rows = 2 x float4
        const float4* py = (const float4*)(y_true + 8 * lp);
        float4 Y0 = py[0], Y1 = py[1];

        acc += row_loss(R.x, R.y,
                        P0.x, P0.y, P0.z, P0.w, P1.x, P1.y,
                        C0.x, C0.y, C1.x,
                        Y0.x, Y0.y, Y0.z, Y0.w);
        acc += row_loss(R.z, R.w,
                        P1.z, P1.w, P2.x, P2.y, P2.z, P2.w,
                        C1.y, C2.x, C2.y,
                        Y1.x, Y1.y, Y1.z, Y1.w);
    }

    // odd tail row (defensive; B = 2M is even)
    if ((n & 1) && blockIdx.x == 0 && threadIdx.x == 0) {
        int i = n - 1;
        acc += row_loss(pred_r[2*i], pred_r[2*i+1],
                        pred_params[6*i], pred_params[6*i+1], pred_params[6*i+2],
                        pred_params[6*i+3], pred_params[6*i+4], pred_params[6*i+5],
                        pred_corr[3*i], pred_corr[3*i+1], pred_corr[3*i+2],
                        y_true[4*i], y_true[4*i+1], y_true[4*i+2], y_true[4*i+3]);
    }

    // ---- intra-block reduce ----
    #pragma unroll
    for (int o = 16; o; o >>= 1)
        acc += __shfl_xor_sync(0xFFFFFFFFu, acc, o);

    __shared__ float warpsums[NTHREADS / 32];
    __shared__ bool  amLast;
    int lane = threadIdx.x & 31;
    int wid  = threadIdx.x >> 5;
    if (lane == 0) warpsums[wid] = acc;
    __syncthreads();

    if (threadIdx.x == 0) {
        double bs = 0.0;
        #pragma unroll
        for (int w = 0; w < NTHREADS / 32; w++) bs += (double)warpsums[w];
        g_partials[blockIdx.x] = bs;
        __threadfence();
        unsigned int t = atomicAdd(&g_counter, 1u);
        amLast = (t == gridDim.x - 1);
    }
    __syncthreads();

    // ---- last block: final reduction (deterministic: fixed order over fixed values) ----
    if (amLast) {
        __shared__ double sh[NTHREADS];
        double s = 0.0;
        volatile double* gp = g_partials;
        for (int i = threadIdx.x; i < NBLOCKS; i += NTHREADS) s += gp[i];
        sh[threadIdx.x] = s;
        __syncthreads();
        for (int st = NTHREADS / 2; st > 0; st >>= 1) {
            if (threadIdx.x < st) sh[threadIdx.x] += sh[threadIdx.x + st];
            __syncthreads();
        }
        if (threadIdx.x == 0) {
            out[0] = (float)(sh[0] / (double)n);
            g_counter = 0;   // reset for next graph replay
        }
    }
}

extern "C" void kernel_launch(void* const* d_in, const int* in_sizes, int n_in,
                              void* d_out, int out_size)
{
    const float* pred_r      = (const float*)d_in[0];
    const float* pred_params = (const float*)d_in[1];
    const float* pred_corr   = (const float*)d_in[2];
    const float* y_true      = (const float*)d_in[3];
    int n = in_sizes[0] / 2;   // pred_r is (B, 2)

    gausscop_fused<<<NBLOCKS, NTHREADS>>>(pred_r, pred_params, pred_corr,
                                          y_true, (float*)d_out, n);
}

// round 3
// speedup vs baseline: 1.0643x; 1.0643x over previous
#include <cuda_runtime.h>
#include <cuda_bf16.h>

#define NBLOCKS 1184
#define NTHREADS 256
#define EPS 0.0001f

__device__ double       g_partials[NBLOCKS];
__device__ unsigned int g_counter = 0;

// Per-row loss. z = clamp((x-u)/s, -3, 3) is the exact simplification of
// sqrt2*erfinv(2*clip(ndtr(t),eps,1-eps)-1) clipped to [-3,3], since
// Phi^-1(eps) = -3.719 < -3 (the eps clip never binds inside [-3,3]).
// nll = 0.5*t^2 + log(s) = 0.5*t^2 + param  (s = exp(param)).
__device__ __forceinline__ float row_loss(
    float ra, float rb,
    float pu1, float ps1, float pu2, float ps2, float pu3, float ps3,
    float r12, float r13, float r23,
    float revert, float Rtop, float Top, float Close)
{
    float u1 = __expf(pu1), s1 = __expf(ps1);
    float u2 = __expf(pu2), s2 = __expf(ps2);
    float u3 = __expf(pu3), s3 = __expf(ps3);

    float t1 = (Rtop  - u1) * __fdividef(1.0f, fmaxf(s1, EPS));
    float t2 = (Top   - u2) * __fdividef(1.0f, fmaxf(s2, EPS));
    float t3 = (Close - u3) * __fdividef(1.0f, fmaxf(s3, EPS));
    float z1 = fminf(fmaxf(t1, -3.0f), 3.0f);
    float z2 = fminf(fmaxf(t2, -3.0f), 3.0f);
    float z3 = fminf(fmaxf(t3, -3.0f), 3.0f);

    float nll_sum = 0.5f * (t1 * t1 + t2 * t2 + t3 * t3) + (ps1 + ps2 + ps3);

    float detR = 1.0f + 2.0f * r12 * r13 * r23
               - r12 * r12 - r13 * r13 - r23 * r23;
    float inv_det = 1.0f / detR;
    float i00 = (1.0f - r23 * r23) * inv_det;
    float i01 = (r13 * r23 - r12) * inv_det;
    float i02 = (r12 * r23 - r13) * inv_det;
    float i11 = (1.0f - r13 * r13) * inv_det;
    float i12 = (r12 * r13 - r23) * inv_det;
    float i22 = (1.0f - r12 * r12) * inv_det;

    float exp_term = 0.5f * ((i00 - 1.0f) * z1 * z1
                           + (i11 - 1.0f) * z2 * z2
                           + (i22 - 1.0f) * z3 * z3)
                   + (i01 * z1 * z2 + i02 * z1 * z3 + i12 * z2 * z3);

    float c_gauss = 0.5f * __logf(fmaxf(detR, EPS)) + exp_term;
    float copula  = revert * (c_gauss + nll_sum);

    float m   = fmaxf(ra, rb);
    float lse = m + __logf(1.0f + __expf(-fabsf(ra - rb)));
    float sel = (revert != 0.0f) ? rb : ra;
    return (lse - sel) + copula;
}

struct RowIn {
    float2 rr; float2 p01, p23, p45; float c0, c1, c2; float4 y;
};

__device__ __forceinline__ RowIn load_row(
    const float* __restrict__ pred_r,
    const float* __restrict__ pred_params,
    const float* __restrict__ pred_corr,
    const float* __restrict__ y_true, long i)
{
    RowIn r;
    r.rr  = *(const float2*)(pred_r      + 2 * i);
    r.p01 = *(const float2*)(pred_params + 6 * i);
    r.p23 = *(const float2*)(pred_params + 6 * i + 2);
    r.p45 = *(const float2*)(pred_params + 6 * i + 4);
    const float* pc = pred_corr + 3 * i;
    r.c0 = pc[0]; r.c1 = pc[1]; r.c2 = pc[2];
    r.y   = *(const float4*)(y_true + 4 * i);
    return r;
}

__global__ __launch_bounds__(NTHREADS, 6)
void gausscop_fused(const float* __restrict__ pred_r,
                    const float* __restrict__ pred_params,
                    const float* __restrict__ pred_corr,
                    const float* __restrict__ y_true,
                    float* __restrict__ out,
                    int n)
{
    const int stride = gridDim.x * blockDim.x;
    const int tid = blockIdx.x * blockDim.x + threadIdx.x;
    float acc = 0.0f;

    int i = tid;
    // main loop: two independent rows per iteration, loads front-batched for MLP
    for (; i + stride < n; i += 2 * stride) {
        RowIn A = load_row(pred_r, pred_params, pred_corr, y_true, i);
        RowIn Bt = load_row(pred_r, pred_params, pred_corr, y_true, i + (long)stride);
        acc += row_loss(A.rr.x, A.rr.y, A.p01.x, A.p01.y, A.p23.x, A.p23.y,
                        A.p45.x, A.p45.y, A.c0, A.c1, A.c2,
                        A.y.x, A.y.y, A.y.z, A.y.w);
        acc += row_loss(Bt.rr.x, Bt.rr.y, Bt.p01.x, Bt.p01.y, Bt.p23.x, Bt.p23.y,
                        Bt.p45.x, Bt.p45.y, Bt.c0, Bt.c1, Bt.c2,
                        Bt.y.x, Bt.y.y, Bt.y.z, Bt.y.w);
    }
    // remainder
    for (; i < n; i += stride) {
        RowIn A = load_row(pred_r, pred_params, pred_corr, y_true, i);
        acc += row_loss(A.rr.x, A.rr.y, A.p01.x, A.p01.y, A.p23.x, A.p23.y,
                        A.p45.x, A.p45.y, A.c0, A.c1, A.c2,
                        A.y.x, A.y.y, A.y.z, A.y.w);
    }

    // ---- intra-block reduce ----
    #pragma unroll
    for (int o = 16; o; o >>= 1)
        acc += __shfl_xor_sync(0xFFFFFFFFu, acc, o);

    __shared__ float warpsums[NTHREADS / 32];
    __shared__ bool  amLast;
    int lane = threadIdx.x & 31;
    int wid  = threadIdx.x >> 5;
    if (lane == 0) warpsums[wid] = acc;
    __syncthreads();

    if (threadIdx.x == 0) {
        double bs = 0.0;
        #pragma unroll
        for (int w = 0; w < NTHREADS / 32; w++) bs += (double)warpsums[w];
        g_partials[blockIdx.x] = bs;
        __threadfence();
        unsigned int t = atomicAdd(&g_counter, 1u);
        amLast = (t == gridDim.x - 1);
    }
    __syncthreads();

    // ---- last block: deterministic final reduction ----
    if (amLast) {
        __shared__ double sh[NTHREADS];
        double s = 0.0;
        volatile double* gp = g_partials;
        for (int k = threadIdx.x; k < NBLOCKS; k += NTHREADS) s += gp[k];
        sh[threadIdx.x] = s;
        __syncthreads();
        for (int st = NTHREADS / 2; st > 0; st >>= 1) {
            if (threadIdx.x < st) sh[threadIdx.x] += sh[threadIdx.x + st];
            __syncthreads();
        }
        if (threadIdx.x == 0) {
            out[0] = (float)(sh[0] / (double)n);
            g_counter = 0;   // reset for next graph replay
        }
    }
}

extern "C" void kernel_launch(void* const* d_in, const int* in_sizes, int n_in,
                              void* d_out, int out_size)
{
    const float* pred_r      = (const float*)d_in[0];
    const float* pred_params = (const float*)d_in[1];
    const float* pred_corr   = (const float*)d_in[2];
    const float* y_true      = (const float*)d_in[3];
    int n = in_sizes[0] / 2;   // pred_r is (B, 2)

    gausscop_fused<<<NBLOCKS, NTHREADS>>>(pred_r, pred_params, pred_corr,
                                          y_true, (float*)d_out, n);
}